// round 10
// baseline (speedup 1.0000x reference)
#include <cuda_runtime.h>
#include <cuda_bf16.h>
#include <cstdint>

// out[m,u] = ||x_m||^2 - 2*(x_m . w_u) + ||w_u||^2
// M = 524288, D = 64, U = 64. bf16 mma.sync m16n8k16 cross term.
// Streaming producer/consumer: ring of 4 x 32KB TMA stages, 1 producer warp
// keeps refills in flight for the whole CTA lifetime; 16 consumer warps each
// process 16-row tiles (consume -> arrive empty -> ldsm -> mma -> epilogue).

#define DEPTH 64
#define UNITS 64
#define CHUNK_ROWS 128
#define CHUNK_BYTES (CHUNK_ROWS * DEPTH * 4)   // 32768
#define RING 4
#define NCHUNK 8                                // chunks per CTA (1024 rows)
#define THREADS 544                             // 16 consumer warps + 1 producer

// dynamic smem layout
#define OFF_STAGE  0                            // 4 x 32768 = 131072
#define OFF_BUF    131072                       // 16 x 2048 = 32768
#define OFF_FRAGB  163840                       // 16*32*16 = 8192
#define OFF_W2     172032                       // 256
#define OFF_X2     172288                       // 16*16*4 = 1024
#define OFF_MBAR   173312                       // 4 full + 4 empty = 64
#define SMEM_TOTAL 173376

__device__ __forceinline__ uint32_t pack_bf16x2(float lo, float hi) {
    uint32_t r;
    asm("cvt.rn.bf16x2.f32 %0, %1, %2;" : "=r"(r) : "f"(hi), "f"(lo));
    return r;
}

__device__ __forceinline__ void mma_bf16(float c[4],
                                         uint32_t a0, uint32_t a1, uint32_t a2, uint32_t a3,
                                         uint32_t b0, uint32_t b1) {
    asm volatile(
        "mma.sync.aligned.m16n8k16.row.col.f32.bf16.bf16.f32 "
        "{%0,%1,%2,%3}, {%4,%5,%6,%7}, {%8,%9}, {%0,%1,%2,%3};"
        : "+f"(c[0]), "+f"(c[1]), "+f"(c[2]), "+f"(c[3])
        : "r"(a0), "r"(a1), "r"(a2), "r"(a3), "r"(b0), "r"(b1));
}

__device__ __forceinline__ void ldsm_x4(uint32_t r[4], uint32_t smem_addr) {
    asm volatile("ldmatrix.sync.aligned.m8n8.x4.shared.b16 {%0,%1,%2,%3}, [%4];"
                 : "=r"(r[0]), "=r"(r[1]), "=r"(r[2]), "=r"(r[3])
                 : "r"(smem_addr));
}

__device__ __forceinline__ uint32_t smem_u32(const void* p) {
    return (uint32_t)__cvta_generic_to_shared(p);
}

__device__ __forceinline__ void mbar_init(uint32_t mbar, uint32_t count) {
    asm volatile("mbarrier.init.shared.b64 [%0], %1;" :: "r"(mbar), "r"(count) : "memory");
}
__device__ __forceinline__ void mbar_arrive(uint32_t mbar) {
    asm volatile("mbarrier.arrive.shared.b64 _, [%0];" :: "r"(mbar) : "memory");
}
__device__ __forceinline__ void mbar_expect_tx(uint32_t mbar, uint32_t bytes) {
    asm volatile("mbarrier.arrive.expect_tx.shared.b64 _, [%0], %1;"
                 :: "r"(mbar), "r"(bytes) : "memory");
}
__device__ __forceinline__ void bulk_copy_g2s(uint32_t dst, const void* src,
                                              uint32_t bytes, uint32_t mbar) {
    asm volatile(
        "cp.async.bulk.shared::cluster.global.mbarrier::complete_tx::bytes "
        "[%0], [%1], %2, [%3];"
        :: "r"(dst), "l"(src), "r"(bytes), "r"(mbar) : "memory");
}
__device__ __forceinline__ void mbar_wait(uint32_t mbar, uint32_t parity) {
    uint32_t done;
    asm volatile(
        "{\n\t.reg .pred p;\n\t"
        "mbarrier.try_wait.parity.acquire.cta.shared::cta.b64 p, [%1], %2;\n\t"
        "selp.b32 %0, 1, 0, p;\n\t}"
        : "=r"(done) : "r"(mbar), "r"(parity) : "memory");
    if (!done) {
        asm volatile(
            "{\n\t.reg .pred P1;\n\t"
            "WAIT_LOOP_%=:\n\t"
            "mbarrier.try_wait.parity.acquire.cta.shared::cta.b64 P1, [%0], %1, 0x989680;\n\t"
            "@P1 bra.uni WAIT_DONE_%=;\n\t"
            "bra.uni WAIT_LOOP_%=;\n\t"
            "WAIT_DONE_%=:\n\t}"
            :: "r"(mbar), "r"(parity) : "memory");
    }
}

__global__ __launch_bounds__(THREADS, 1) void sqdist_kernel(
    const float* __restrict__ x, const float* __restrict__ w,
    float* __restrict__ out)
{
    extern __shared__ __align__(16) char smem[];
    float* stage = reinterpret_cast<float*>(smem + OFF_STAGE);
    uint4 (*fragB4)[32] = reinterpret_cast<uint4(*)[32]>(smem + OFF_FRAGB);
    float* w2_s  = reinterpret_cast<float*>(smem + OFF_W2);
    float* x2s   = reinterpret_cast<float*>(smem + OFF_X2);   // [16][16]
    const uint32_t mb_full  = smem_u32(smem + OFF_MBAR);       // 4 x 8B
    const uint32_t mb_empty = mb_full + 32;                    // 4 x 8B

    const int tid  = threadIdx.x;
    const int warp = tid >> 5;        // 0..16
    const int lane = tid & 31;

    const long ctarow = (long)blockIdx.x * (CHUNK_ROWS * NCHUNK);
    const float* xbase = x + ctarow * DEPTH;

    // ---- mbarrier init + first RING chunk fills issued immediately.
    if (tid == 0) {
        #pragma unroll
        for (int s = 0; s < RING; s++) {
            mbar_init(mb_full + s * 8, 1);
            mbar_init(mb_empty + s * 8, 8);
        }
        // fence not required before TMA on same thread after init+syncthreads;
        // but issue fills after init in program order (same thread = ordered).
        #pragma unroll
        for (int c = 0; c < RING; c++) {
            mbar_expect_tx(mb_full + c * 8, CHUNK_BYTES);
            bulk_copy_g2s(smem_u32(stage + c * 8192),
                          xbase + (long)c * CHUNK_ROWS * DEPTH,
                          CHUNK_BYTES, mb_full + c * 8);
        }
    }

    // ---- Prologue: w2 (threads 0..255)
    if (tid < 256) {
        const int n  = tid >> 2;
        const int dq = (tid & 3) * 16;
        const float* wp = w + n * DEPTH + dq;
        float psum = 0.f;
        #pragma unroll
        for (int i = 0; i < 4; i++) {
            float4 v = reinterpret_cast<const float4*>(wp)[i];
            psum += v.x * v.x + v.y * v.y + v.z * v.z + v.w * v.w;
        }
        psum += __shfl_xor_sync(0xffffffffu, psum, 1);
        psum += __shfl_xor_sync(0xffffffffu, psum, 2);
        if ((tid & 3) == 0) w2_s[n] = psum;
    }

    // ---- Prologue: pack w into uint4 B-fragments (threads 0..511, 1 each).
    if (tid < 512) {
        const int e   = tid;
        const int l   = e & 31;
        const int idx = e >> 5;          // nt*2 + kh
        const int kh  = idx & 1;
        const int nt  = idx >> 1;
        const int n   = nt * 8 + (l >> 2);
        const int k0  = (2 * kh) * 16 + (l & 3) * 2;
        const float* wn = w + n * DEPTH;
        float2 a0 = *reinterpret_cast<const float2*>(wn + k0);
        float2 a1 = *reinterpret_cast<const float2*>(wn + k0 + 8);
        float2 b0 = *reinterpret_cast<const float2*>(wn + k0 + 16);
        float2 b1 = *reinterpret_cast<const float2*>(wn + k0 + 24);
        uint4 f;
        f.x = pack_bf16x2(a0.x, a0.y);
        f.y = pack_bf16x2(a1.x, a1.y);
        f.z = pack_bf16x2(b0.x, b0.y);
        f.w = pack_bf16x2(b1.x, b1.y);
        fragB4[idx][l] = f;
    }
    __syncthreads();   // fragB, w2, mbar inits visible to all warps

    if (warp == 16) {
        // ================= PRODUCER WARP =================
        if (lane == 0) {
            for (int c = RING; c < NCHUNK; c++) {
                const int s = c & (RING - 1);
                const uint32_t pe = ((c - RING) >> 2) & 1;   // empty-phase parity
                mbar_wait(mb_empty + s * 8, pe);
                mbar_expect_tx(mb_full + s * 8, CHUNK_BYTES);
                bulk_copy_g2s(smem_u32(stage + s * 8192),
                              xbase + (long)c * CHUNK_ROWS * DEPTH,
                              CHUNK_BYTES, mb_full + s * 8);
            }
        }
        return;
    }

    // ================= CONSUMER WARPS (0..15) =================
    const int g  = lane >> 2;
    const int t4 = lane & 3;
    char* buf = smem + OFF_BUF + warp * 2048;
    float2* stage2 = reinterpret_cast<float2*>(buf);   // 8 rows x 32 float2
    const int jj   = lane & 15;
    const int rhal = lane >> 4;

    // Register-cached B fragments for nt 0..3 (whole-kernel reuse).
    uint4 Br[8];
    #pragma unroll
    for (int idx = 0; idx < 8; idx++) Br[idx] = fragB4[idx][lane];

    // 4 iterations; each iteration consumes 2 chunks (warps 0-7 -> chunk 2it,
    // warps 8-15 -> chunk 2it+1).
    #pragma unroll 1
    for (int it = 0; it < NCHUNK / 2; it++) {
        const int cid = 2 * it + (warp >> 3);         // chunk id 0..7
        const int s   = cid & (RING - 1);
        const uint32_t pf = (cid >> 2) & 1;           // full-phase parity
        mbar_wait(mb_full + s * 8, pf);

        // ---- Consume 16-row tile: tile-contiguous LDS.128 -> sq + bf16 pack.
        const float4* xt = reinterpret_cast<const float4*>(
            stage + s * 8192 + (warp & 7) * (16 * DEPTH));
        float sq[8];
        #pragma unroll
        for (int i = 0; i < 8; i++) {
            const int ci = i * 32 + lane;
            float4 v = xt[ci];
            sq[i] = v.x * v.x + v.y * v.y + v.z * v.z + v.w * v.w;
            const int r     = ci >> 4;
            const int col4  = ci & 15;
            const int ch    = col4 >> 1;
            const int half8 = col4 & 1;
            const int rx    = (r & 7) ^ ((r & 8) >> 1);
            uint2 h;
            h.x = pack_bf16x2(v.x, v.y);
            h.y = pack_bf16x2(v.z, v.w);
            *reinterpret_cast<uint2*>(buf + r * 128 + ((ch ^ rx) * 16) + half8 * 8) = h;
        }
        __syncwarp();
        // All stage reads for this warp are done -> release the stage.
        if (lane == 0) mbar_arrive(mb_empty + s * 8);

        // ---- A fragments via ldmatrix.x4.
        uint32_t ab[4][4];
        {
            const int row   = (lane & 7) + ((lane >> 3) & 1) * 8;
            const int chsel = (lane >> 4);
            const int rx    = (row & 7) ^ ((row & 8) >> 1);
            const uint32_t base = smem_u32(buf + row * 128);
            #pragma unroll
            for (int kb = 0; kb < 4; kb++) {
                const int phys = (2 * kb + chsel) ^ rx;
                ldsm_x4(ab[kb], base + phys * 16);
            }
        }

        // ---- x2 reductions.
        #pragma unroll
        for (int i = 0; i < 8; i++) {
            sq[i] += __shfl_xor_sync(0xffffffffu, sq[i], 1);
            sq[i] += __shfl_xor_sync(0xffffffffu, sq[i], 2);
            sq[i] += __shfl_xor_sync(0xffffffffu, sq[i], 4);
            sq[i] += __shfl_xor_sync(0xffffffffu, sq[i], 8);
        }
        if (lane == 0) {
            #pragma unroll
            for (int i = 0; i < 8; i++) x2s[warp * 16 + 2 * i] = sq[i];
        } else if (lane == 16) {
            #pragma unroll
            for (int i = 0; i < 8; i++) x2s[warp * 16 + 2 * i + 1] = sq[i];
        }
        __syncwarp();

        // ---- GEMM: nt 0..3 B from registers, nt 4..7 from smem.
        float acc[8][4];
        #pragma unroll
        for (int nt = 0; nt < 4; nt++) {
            acc[nt][0] = acc[nt][1] = acc[nt][2] = acc[nt][3] = 0.f;
            uint4 bA = Br[nt * 2];
            uint4 bB = Br[nt * 2 + 1];
            mma_bf16(acc[nt], ab[0][0], ab[0][1], ab[0][2], ab[0][3], bA.x, bA.y);
            mma_bf16(acc[nt], ab[1][0], ab[1][1], ab[1][2], ab[1][3], bA.z, bA.w);
            mma_bf16(acc[nt], ab[2][0], ab[2][1], ab[2][2], ab[2][3], bB.x, bB.y);
            mma_bf16(acc[nt], ab[3][0], ab[3][1], ab[3][2], ab[3][3], bB.z, bB.w);
        }
        #pragma unroll
        for (int nt = 4; nt < 8; nt++) {
            acc[nt][0] = acc[nt][1] = acc[nt][2] = acc[nt][3] = 0.f;
            uint4 bA = fragB4[nt * 2][lane];
            uint4 bB = fragB4[nt * 2 + 1][lane];
            mma_bf16(acc[nt], ab[0][0], ab[0][1], ab[0][2], ab[0][3], bA.x, bA.y);
            mma_bf16(acc[nt], ab[1][0], ab[1][1], ab[1][2], ab[1][3], bA.z, bA.w);
            mma_bf16(acc[nt], ab[2][0], ab[2][1], ab[2][2], ab[2][3], bB.x, bB.y);
            mma_bf16(acc[nt], ab[3][0], ab[3][1], ab[3][2], ab[3][3], bB.z, bB.w);
        }
        __syncwarp();   // bf16 tile reads done; buf reused as epilogue stage

        // ---- Epilogue: out = x2 + w2 - 2*acc, per-pass staged -> STG.128.
        const long row0 = ctarow + (long)cid * CHUNK_ROWS + (warp & 7) * 16;
        const float p_lo = x2s[warp * 16 + g];
        const float p_hi = x2s[warp * 16 + g + 8];
        #pragma unroll
        for (int pass = 0; pass < 2; pass++) {
            const float p = pass ? p_hi : p_lo;
            #pragma unroll
            for (int nt = 0; nt < 8; nt++) {
                const int ucol = nt * 8 + t4 * 2;
                float2 w2v = *reinterpret_cast<const float2*>(&w2_s[ucol]);
                float2 o;
                o.x = p + w2v.x - 2.f * acc[nt][2 * pass];
                o.y = p + w2v.y - 2.f * acc[nt][2 * pass + 1];
                const int sidx = nt * 4 + t4;
                stage2[g * 32 + (sidx ^ ((g & 3) * 4))] = o;
            }
            __syncwarp();
            #pragma unroll
            for (int s8 = 0; s8 < 4; s8++) {
                const int r = s8 * 2 + rhal;
                const int phys = (2 * jj) ^ ((r & 3) * 4);
                float4 v = *reinterpret_cast<const float4*>(&stage2[r * 32 + phys]);
                const long grow = row0 + pass * 8 + r;
                __stcs(reinterpret_cast<float4*>(out + grow * UNITS + jj * 4), v);
            }
            __syncwarp();
        }
    }
}

extern "C" void kernel_launch(void* const* d_in, const int* in_sizes, int n_in,
                              void* d_out, int out_size) {
    const float* x = (const float*)d_in[0];
    const float* w = (const float*)d_in[1];
    float* out = (float*)d_out;
    cudaFuncSetAttribute(sqdist_kernel,
                         cudaFuncAttributeMaxDynamicSharedMemorySize, SMEM_TOTAL);
    const int M = in_sizes[0] / DEPTH;                 // 524288
    const int grid = M / (CHUNK_ROWS * NCHUNK);        // 512
    sqdist_kernel<<<grid, THREADS, SMEM_TOTAL>>>(x, w, out);
}